// round 5
// baseline (speedup 1.0000x reference)
#include <cuda_runtime.h>
#include <cuda_bf16.h>
#include <math.h>
#include <stdint.h>

#define B 128
#define S 512
#define T 256
#define THREADS 640          // 512 LSE threads + 128 Viterbi threads
#define L2E 1.4426950408889634f
#define NEG_INF (-__int_as_float(0x7f800000))

#define BAR_LSE() asm volatile("bar.sync 1, 512;" ::: "memory")
#define BAR_VIT() asm volatile("bar.sync 2, 128;" ::: "memory")

// ---------------- device scratch (static, no allocation) ----------------
__device__ __align__(16) unsigned char g_hist[(size_t)S * B * T]; // [(t*B + b)*T + j]
__device__ float g_den[B];
__device__ float g_num[B];

// ---------------- shared memory layout (bytes) ----------------
#define OFF_HIST   0         // backtrack staging (reuses 131072 bytes)
#define OFF_P      131072    // float P[T]                   1024
#define OFF_DS     132096    // float ds[T]                  1024
#define OFF_ACC    133120    // float accp[8*T]              8192
#define OFF_REDF   141312    // float redf[32] (dbl-buf 2x8 in loop) 128
#define OFF_REDI   141440    // int   redi[32]               128
#define OFF_IBC    141584    // int   ibc[4]                 16
#define OFF_VS     141600    // float vs[T]                  1024
#define OFF_RMAX   142624    // float rowmax[T]              1024
#define OFF_RMIN   143648    // float rowmin[T]              1024
#define OFF_CI     144672    // int   cand_i[T]              1024
#define OFF_CV     145696    // float cand_v[T]              1024
#define OFF_VRED   146720    // float vred[8]                32
#define OFF_WCNT   146752    // int   wcnt[8]                32
#define OFF_VIBC   146784    // int   vibc[4]                16
#define SMEM_BYTES 146944

__device__ __forceinline__ unsigned bf16_rn(float f) {
    unsigned int u = __float_as_uint(f);
    return (u + 0x7fffu + ((u >> 16) & 1u)) >> 16;
}

__global__ void __launch_bounds__(THREADS, 1)
crf_main(const float* __restrict__ logits, const int* __restrict__ mask,
         const float* __restrict__ start_t, const float* __restrict__ end_t,
         const float* __restrict__ trans, float* __restrict__ out) {
    extern __shared__ char sm[];
    float*          Psm   = (float*)(sm + OFF_P);
    float*          dsbuf = (float*)(sm + OFF_DS);
    float*          accp  = (float*)(sm + OFF_ACC);
    float*          redf  = (float*)(sm + OFF_REDF);
    int*            redi  = (int*)(sm + OFF_REDI);
    int*            ibc   = (int*)(sm + OFF_IBC);
    float*          vssm  = (float*)(sm + OFF_VS);
    float*          rmax  = (float*)(sm + OFF_RMAX);
    float*          rmin  = (float*)(sm + OFF_RMIN);
    int*            cidx  = (int*)(sm + OFF_CI);
    float*          cval  = (float*)(sm + OFF_CV);
    float*          vred  = (float*)(sm + OFF_VRED);
    int*            wcnt  = (int*)(sm + OFF_WCNT);
    int*            vibc  = (int*)(sm + OFF_VIBC);

    const int b    = blockIdx.x;
    const int tid  = threadIdx.x;
    const int wid  = tid >> 5;
    const int lane = tid & 31;
    const float* gl = logits + (size_t)b * S * T;
    const int* mrow = mask + (size_t)b * S;

    // ================= init (full block) =================
    {
        int cnt = 0;
        for (int s = tid; s < S; s += THREADS) cnt += (mrow[s] != 0);
        #pragma unroll
        for (int o = 16; o; o >>= 1) cnt += __shfl_xor_sync(0xffffffffu, cnt, o);
        if (lane == 0) redi[wid] = cnt;
    }
    // row max / min of trans (threads 0..255)
    if (tid < T) {
        float mx = NEG_INF, mn = -NEG_INF;
        const float4* tr4 = (const float4*)(trans + (size_t)tid * T);
        #pragma unroll 8
        for (int c = 0; c < T / 4; ++c) {
            float4 v = tr4[c];
            mx = fmaxf(fmaxf(mx, v.x), fmaxf(v.y, fmaxf(v.z, v.w)));
            mn = fminf(fminf(mn, v.x), fminf(v.y, fminf(v.z, v.w)));
        }
        rmax[tid] = mx;
        rmin[tid] = mn;
    }
    __syncthreads();
    if (tid == 0) {
        int s = 0;
        #pragma unroll
        for (int w = 0; w < THREADS / 32; ++w) s += redi[w];
        ibc[0] = s;
    }
    // t = 0: ds0 = vs0 = start + logits[0]
    float ds0 = NEG_INF;
    if (tid < T) {
        ds0 = start_t[tid] + gl[tid];
        dsbuf[tid] = ds0;
        vssm[tid]  = ds0;
    }
    {
        float v = ds0;
        #pragma unroll
        for (int o = 16; o; o >>= 1) v = fmaxf(v, __shfl_xor_sync(0xffffffffu, v, o));
        if (wid < 8 && lane == 0) redf[wid] = v;   // buffer 0 for t=1
    }
    __syncthreads();
    float m0 = redf[0];
    #pragma unroll
    for (int w = 1; w < 8; ++w) m0 = fmaxf(m0, redf[w]);
    if (tid < T) Psm[tid] = exp2f((ds0 - m0) * L2E);
    const int L = ibc[0];
    __syncthreads();

    // ================= specialized main loops =================
    if (tid < 512) {
        // ---------------- LSE group (16 warps), register-resident E ----------------
        const int jg4 = (tid & 63) * 4;
        const int i0  = (tid >> 6) * 32;
        const int is  = tid >> 6;

        // E tile in registers: eR[2*ii+0] packs (e[i0+ii][jg4+1]<<16 | e[..][jg4+0]),
        //                      eR[2*ii+1] packs (jg4+3, jg4+2)
        unsigned eR[64];
        {
            const float* trow = trans + (size_t)i0 * T + jg4;
            #pragma unroll
            for (int ii = 0; ii < 32; ++ii) {
                float4 tr = *(const float4*)(trow + (size_t)ii * T);
                eR[2 * ii + 0] = (bf16_rn(expf(tr.y)) << 16) | bf16_rn(expf(tr.x));
                eR[2 * ii + 1] = (bf16_rn(expf(tr.w)) << 16) | bf16_rn(expf(tr.z));
            }
        }
        const float* Prow  = Psm + i0;
        float*       accw  = accp + is * T + jg4;
        float m_P = m0;   // shift used in current Psm

        for (int t = 1; t < L; ++t) {
            float emit = 0.f;
            if (tid < T) emit = gl[(size_t)t * T + tid];   // prefetch

            float a0 = 0.f, a1 = 0.f, a2 = 0.f, a3 = 0.f;
            #pragma unroll
            for (int ii = 0; ii < 32; ii += 4) {
                float4 p4 = *(const float4*)(Prow + ii);   // broadcast
                #define ROWFMA(K, PP)                                              \
                {   unsigned u0 = eR[2*(ii+K)+0], u1 = eR[2*(ii+K)+1];             \
                    a0 = fmaf(PP, __uint_as_float(u0 << 16), a0);                  \
                    a1 = fmaf(PP, __uint_as_float(u0), a1);                        \
                    a2 = fmaf(PP, __uint_as_float(u1 << 16), a2);                  \
                    a3 = fmaf(PP, __uint_as_float(u1), a3);  }
                ROWFMA(0, p4.x)
                ROWFMA(1, p4.y)
                ROWFMA(2, p4.z)
                ROWFMA(3, p4.w)
                #undef ROWFMA
            }
            *(float4*)accw = make_float4(a0, a1, a2, a3);
            BAR_LSE();

            if (tid < T) {
                float asum = 0.f;
                #pragma unroll
                for (int s2 = 0; s2 < 8; ++s2) asum += accp[s2 * T + tid];
                // stale max from previous step (double-buffered)
                const float* rr = redf + (((t - 1) & 1) << 3);
                float mnext = rr[0];
                #pragma unroll
                for (int w = 1; w < 8; ++w) mnext = fmaxf(mnext, rr[w]);
                float dsn = m_P + logf(asum) + emit;
                dsbuf[tid] = dsn;
                float wmax = dsn;
                #pragma unroll
                for (int o = 16; o; o >>= 1) wmax = fmaxf(wmax, __shfl_xor_sync(0xffffffffu, wmax, o));
                if (lane == 0) redf[((t & 1) << 3) + wid] = wmax;
                Psm[tid] = exp2f((dsn - mnext) * L2E);
                m_P = mnext;
            }
            BAR_LSE();
        }
    } else {
        // ---------------- Viterbi group (4 warps, certified pruning) ----------------
        const int vtid  = tid - 512;        // 0..127
        const int vwid  = vtid >> 5;
        const int vlane = vtid & 31;
        const int j0  = 2 * vtid;           // owns columns j0, j0+1
        const int i0c = 2 * vtid;           // screens rows i0c, i0c+1

        for (int t = 1; t < L; ++t) {
            float2 em  = *(const float2*)(gl + (size_t)t * T + j0);
            float2 v2  = *(const float2*)(vssm + i0c);
            float2 rn2 = *(const float2*)(rmin + i0c);
            float2 rx2 = *(const float2*)(rmax + i0c);

            float sthr = fmaxf(v2.x + rn2.x, v2.y + rn2.y);
            #pragma unroll
            for (int o = 16; o; o >>= 1) sthr = fmaxf(sthr, __shfl_xor_sync(0xffffffffu, sthr, o));
            if (vlane == 0) vred[vwid] = sthr;
            BAR_VIT();
            float thresh = fmaxf(fmaxf(vred[0], vred[1]), fmaxf(vred[2], vred[3]));

            int q0 = (v2.x + rx2.x >= thresh) ? 1 : 0;
            int q1 = (v2.y + rx2.y >= thresh) ? 1 : 0;
            int cnt = q0 + q1;
            int incl = cnt;
            #pragma unroll
            for (int o = 1; o < 32; o <<= 1) {
                int n = __shfl_up_sync(0xffffffffu, incl, o);
                if (vlane >= o) incl += n;
            }
            int excl = incl - cnt;
            if (vlane == 31) wcnt[vwid] = incl;
            BAR_VIT();
            int base = 0;
            #pragma unroll
            for (int w = 0; w < 4; ++w) base += (w < vwid) ? wcnt[w] : 0;
            int nc = wcnt[0] + wcnt[1] + wcnt[2] + wcnt[3];
            int pos = base + excl;
            if (q0) { cidx[pos] = i0c;     cval[pos] = v2.x; pos++; }
            if (q1) { cidx[pos] = i0c + 1; cval[pos] = v2.y; }
            BAR_VIT();

            float b1 = NEG_INF, b2 = NEG_INF;
            int x1 = 0, x2 = 0;
            int c = 0;
            for (; c + 4 <= nc; c += 4) {
                int   ia = cidx[c], ibx = cidx[c+1], ic = cidx[c+2], id = cidx[c+3];
                float va = cval[c], vb = cval[c+1], vc = cval[c+2], vd = cval[c+3];
                float2 ta = *(const float2*)(trans + (size_t)ia  * T + j0);
                float2 tb = *(const float2*)(trans + (size_t)ibx * T + j0);
                float2 tc = *(const float2*)(trans + (size_t)ic  * T + j0);
                float2 td = *(const float2*)(trans + (size_t)id  * T + j0);
                float c1, c2;
                c1 = va + ta.x; if (c1 > b1) { b1 = c1; x1 = ia; }
                c2 = va + ta.y; if (c2 > b2) { b2 = c2; x2 = ia; }
                c1 = vb + tb.x; if (c1 > b1) { b1 = c1; x1 = ibx; }
                c2 = vb + tb.y; if (c2 > b2) { b2 = c2; x2 = ibx; }
                c1 = vc + tc.x; if (c1 > b1) { b1 = c1; x1 = ic; }
                c2 = vc + tc.y; if (c2 > b2) { b2 = c2; x2 = ic; }
                c1 = vd + td.x; if (c1 > b1) { b1 = c1; x1 = id; }
                c2 = vd + td.y; if (c2 > b2) { b2 = c2; x2 = id; }
            }
            for (; c < nc; ++c) {
                int   ia = cidx[c];
                float va = cval[c];
                float2 ta = *(const float2*)(trans + (size_t)ia * T + j0);
                float c1 = va + ta.x; if (c1 > b1) { b1 = c1; x1 = ia; }
                float c2 = va + ta.y; if (c2 > b2) { b2 = c2; x2 = ia; }
            }

            *(float2*)(vssm + j0) = make_float2(b1 + em.x, b2 + em.y);
            *(unsigned short*)(g_hist + ((size_t)t * B + b) * T + j0) =
                (unsigned short)((unsigned)x1 | ((unsigned)x2 << 8));
            BAR_VIT();
        }
    }
    __syncthreads();   // join groups

    // ================= epilogue (full block) =================
    // denominator: logsumexp(ds + end)
    {
        float xd = NEG_INF;
        if (tid < T) xd = dsbuf[tid] + end_t[tid];
        float v = xd;
        #pragma unroll
        for (int o = 16; o; o >>= 1) v = fmaxf(v, __shfl_xor_sync(0xffffffffu, v, o));
        if (lane == 0) redf[wid] = v;
        __syncthreads();
        float m2 = redf[0];
        #pragma unroll
        for (int w = 1; w < THREADS / 32; ++w) m2 = fmaxf(m2, redf[w]);
        float cs = (tid < T) ? exp2f((xd - m2) * L2E) : 0.f;
        #pragma unroll
        for (int o = 16; o; o >>= 1) cs += __shfl_xor_sync(0xffffffffu, cs, o);
        __syncthreads();
        if (lane == 0) redf[wid] = cs;
        __syncthreads();
        if (tid == 0) {
            float ssum = 0.f;
            #pragma unroll
            for (int w = 0; w < THREADS / 32; ++w) ssum += redf[w];
            g_den[b] = m2 + logf(ssum);
        }
    }
    // viterbi last tag: argmax(vs + end), lowest index on ties
    {
        float xv = NEG_INF;
        int idx = 0x7fffffff;
        if (tid < T) { xv = vssm[tid] + end_t[tid]; idx = tid; }
        #pragma unroll
        for (int o = 16; o; o >>= 1) {
            float ov = __shfl_xor_sync(0xffffffffu, xv, o);
            int   oi = __shfl_xor_sync(0xffffffffu, idx, o);
            if (ov > xv || (ov == xv && oi < idx)) { xv = ov; idx = oi; }
        }
        __syncthreads();
        if (lane == 0) { redf[wid] = xv; redi[wid] = idx; }
        __syncthreads();
        if (tid == 0) {
            float bv = redf[0]; int bi = redi[0];
            #pragma unroll
            for (int w = 1; w < THREADS / 32; ++w) {
                float ov = redf[w]; int oi = redi[w];
                if (ov > bv || (ov == bv && oi < bi)) { bv = ov; bi = oi; }
            }
            vibc[0] = bi;
        }
        __syncthreads();
    }
    const int last = vibc[0];

    // backtrack: stage this batch's history into SMEM
    unsigned char* hsm = (unsigned char*)(sm + OFF_HIST);   // L*T <= 131072
    for (int f = tid; f < L * (T / 16); f += THREADS) {
        int row = f >> 4;
        int off = f & 15;
        ((uint4*)hsm)[f] = ((const uint4*)(g_hist + ((size_t)row * B + b) * T))[off];
    }
    __syncthreads();

    float* outp = out + (size_t)b * S;
    for (int s = L + tid; s < S; s += THREADS) outp[s] = 0.0f;  // masked -> 0
    if (tid == 0) {
        int tag = last;
        outp[L - 1] = (float)tag;
        for (int t = L - 2; t >= 0; --t) {
            tag = hsm[(t + 1) * T + tag];
            outp[t] = (float)tag;
        }
    }
}

// ---------------- numerator ----------------
__global__ void __launch_bounds__(256)
crf_num(const float* __restrict__ logits, const int* __restrict__ mask,
        const int* __restrict__ labels, const float* __restrict__ start_t,
        const float* __restrict__ end_t, const float* __restrict__ trans) {
    __shared__ float redf[8];
    __shared__ int   redi[8];
    const int b = blockIdx.x;
    const int tid = threadIdx.x;
    const int* lab = labels + (size_t)b * S;
    const float* gl = logits + (size_t)b * S * T;
    const int* mrow = mask + (size_t)b * S;

    float part = 0.f;
    int cnt = 0;
    for (int s = tid; s < S; s += 256) cnt += (mrow[s] != 0);
    for (int s = 1 + tid; s < S; s += 256) {
        if (mrow[s]) {
            int ls = lab[s];
            int lp = lab[s - 1];
            part += trans[lp * T + ls] + gl[(size_t)s * T + ls];
        }
    }
    #pragma unroll
    for (int o = 16; o; o >>= 1) {
        part += __shfl_xor_sync(0xffffffffu, part, o);
        cnt  += __shfl_xor_sync(0xffffffffu, cnt, o);
    }
    if ((tid & 31) == 0) { redf[tid >> 5] = part; redi[tid >> 5] = cnt; }
    __syncthreads();
    if (tid == 0) {
        float s = 0.f; int L = 0;
        #pragma unroll
        for (int w = 0; w < 8; ++w) { s += redf[w]; L += redi[w]; }
        int l0 = lab[0];
        int ll = lab[L - 1];
        g_num[b] = s + start_t[l0] + gl[l0] + end_t[ll];
    }
}

// ---------------- loss ----------------
__global__ void __launch_bounds__(128)
crf_loss(float* __restrict__ out) {
    __shared__ float redf[4];
    const int tid = threadIdx.x;
    float d = g_num[tid] - g_den[tid];
    #pragma unroll
    for (int o = 16; o; o >>= 1) d += __shfl_xor_sync(0xffffffffu, d, o);
    if ((tid & 31) == 0) redf[tid >> 5] = d;
    __syncthreads();
    if (tid == 0) {
        float s = redf[0] + redf[1] + redf[2] + redf[3];
        out[(size_t)B * S] = -(s / (float)B);
    }
}

// ---------------- launch ----------------
extern "C" void kernel_launch(void* const* d_in, const int* in_sizes, int n_in,
                              void* d_out, int out_size) {
    const float* logits = (const float*)d_in[0];
    const int*   mask   = (const int*)d_in[1];
    const int*   labels = (const int*)d_in[2];
    const float* start  = (const float*)d_in[3];
    const float* endt   = (const float*)d_in[4];
    const float* trans  = (const float*)d_in[5];
    float*       out    = (float*)d_out;

    cudaFuncSetAttribute(crf_main, cudaFuncAttributeMaxDynamicSharedMemorySize, SMEM_BYTES);

    crf_main<<<B, THREADS, SMEM_BYTES>>>(logits, mask, start, endt, trans, out);
    crf_num<<<B, 256>>>(logits, mask, labels, start, endt, trans);
    crf_loss<<<1, 128>>>(out);
}

// round 6
// speedup vs baseline: 1.6142x; 1.6142x over previous
#include <cuda_runtime.h>
#include <cuda_bf16.h>
#include <math.h>
#include <stdint.h>

#define B 128
#define S 512
#define T 256
#define THREADS 640          // 512 LSE threads + 128 Viterbi threads
#define REG_ROWS 24          // rows of per-thread E tile kept in registers
#define L2E 1.4426950408889634f
#define NEG_INF (-__int_as_float(0x7f800000))

#define BAR_LSE() asm volatile("bar.sync 1, 512;" ::: "memory")
#define BAR_VIT() asm volatile("bar.sync 2, 128;" ::: "memory")

// ---------------- device scratch (static, no allocation) ----------------
__device__ __align__(16) unsigned char g_hist[(size_t)S * B * T]; // [(t*B + b)*T + j]
__device__ float g_den[B];
__device__ float g_num[B];

// ---------------- shared memory layout (bytes) ----------------
// Loop-only region [0, 131072) — reused by backtrack staging afterwards.
#define OFF_EH     0         // ushort E-hybrid [8 slices][8 rows][256 cols] 32768
#define OFF_P      32768     // float P[T]                    1024
#define OFF_ACC    33792     // float accp[8*T]               8192
#define OFF_CI     41984     // int   cand_i[T]               1024
#define OFF_CV     43008     // float cand_v[T]               1024
#define OFF_VRED   44032     // float vred[8]                 32
#define OFF_WCNT   44064     // int   wcnt[8]                 32
// Persistent region [131072, ...)
#define OFF_DS     131072    // float ds[T]                   1024
#define OFF_VS     132096    // float vs[T]                   1024
#define OFF_RMAX   133120    // float rowmax[T]               1024
#define OFF_RMIN   134144    // float rowmin[T]               1024
#define OFF_REDF   135168    // float redf[32] (dbl-buf 2x8)  128
#define OFF_REDI   135296    // int   redi[32]                128
#define OFF_IBC    135424    // int   ibc[4]                  16
#define OFF_VIBC   135440    // int   vibc[4]                 16
#define SMEM_BYTES 135488

__device__ __forceinline__ unsigned bf16_rn(float f) {
    unsigned int u = __float_as_uint(f);
    return (u + 0x7fffu + ((u >> 16) & 1u)) >> 16;
}

__global__ void __launch_bounds__(THREADS, 1)
crf_main(const float* __restrict__ logits, const int* __restrict__ mask,
         const float* __restrict__ start_t, const float* __restrict__ end_t,
         const float* __restrict__ trans, float* __restrict__ out) {
    extern __shared__ char sm[];
    unsigned short* EsmH  = (unsigned short*)(sm + OFF_EH);
    float*          Psm   = (float*)(sm + OFF_P);
    float*          accp  = (float*)(sm + OFF_ACC);
    int*            cidx  = (int*)(sm + OFF_CI);
    float*          cval  = (float*)(sm + OFF_CV);
    float*          vred  = (float*)(sm + OFF_VRED);
    int*            wcnt  = (int*)(sm + OFF_WCNT);
    float*          dsbuf = (float*)(sm + OFF_DS);
    float*          vssm  = (float*)(sm + OFF_VS);
    float*          rmax  = (float*)(sm + OFF_RMAX);
    float*          rmin  = (float*)(sm + OFF_RMIN);
    float*          redf  = (float*)(sm + OFF_REDF);
    int*            redi  = (int*)(sm + OFF_REDI);
    int*            ibc   = (int*)(sm + OFF_IBC);
    int*            vibc  = (int*)(sm + OFF_VIBC);

    const int b    = blockIdx.x;
    const int tid  = threadIdx.x;
    const int wid  = tid >> 5;
    const int lane = tid & 31;
    const float* gl = logits + (size_t)b * S * T;
    const int* mrow = mask + (size_t)b * S;

    // ================= init (full block) =================
    {
        int cnt = 0;
        for (int s = tid; s < S; s += THREADS) cnt += (mrow[s] != 0);
        #pragma unroll
        for (int o = 16; o; o >>= 1) cnt += __shfl_xor_sync(0xffffffffu, cnt, o);
        if (lane == 0) redi[wid] = cnt;
    }
    // row max / min of trans (threads 0..255)
    if (tid < T) {
        float mx = NEG_INF, mn = -NEG_INF;
        const float4* tr4 = (const float4*)(trans + (size_t)tid * T);
        #pragma unroll 8
        for (int c = 0; c < T / 4; ++c) {
            float4 v = tr4[c];
            mx = fmaxf(fmaxf(mx, v.x), fmaxf(v.y, fmaxf(v.z, v.w)));
            mn = fminf(fminf(mn, v.x), fminf(v.y, fminf(v.z, v.w)));
        }
        rmax[tid] = mx;
        rmin[tid] = mn;
    }
    __syncthreads();
    if (tid == 0) {
        int s = 0;
        #pragma unroll
        for (int w = 0; w < THREADS / 32; ++w) s += redi[w];
        ibc[0] = s;
    }
    // t = 0: ds0 = vs0 = start + logits[0]
    float ds0 = NEG_INF;
    if (tid < T) {
        ds0 = start_t[tid] + gl[tid];
        dsbuf[tid] = ds0;
        vssm[tid]  = ds0;
    }
    {
        float v = ds0;
        #pragma unroll
        for (int o = 16; o; o >>= 1) v = fmaxf(v, __shfl_xor_sync(0xffffffffu, v, o));
        if (wid < 8 && lane == 0) redf[wid] = v;   // buffer 0 for t=1
    }
    __syncthreads();
    float m0 = redf[0];
    #pragma unroll
    for (int w = 1; w < 8; ++w) m0 = fmaxf(m0, redf[w]);
    if (tid < T) Psm[tid] = exp2f((ds0 - m0) * L2E);
    const int L = ibc[0];
    __syncthreads();

    // ================= specialized main loops =================
    if (tid < 512) {
        // ------- LSE group (16 warps): E tile 32 rows x 4 cols per thread,
        //         rows 0..23 in registers, rows 24..31 in SMEM (bf16) -------
        const int jg4 = (tid & 63) * 4;
        const int is  = tid >> 6;
        const int i0  = is * 32;

        unsigned eR[REG_ROWS * 2];
        {
            const float* trow = trans + (size_t)i0 * T + jg4;
            #pragma unroll
            for (int r = 0; r < REG_ROWS; ++r) {
                float4 tr = *(const float4*)(trow + (size_t)r * T);
                eR[2 * r + 0] = (bf16_rn(expf(tr.y)) << 16) | bf16_rn(expf(tr.x));
                eR[2 * r + 1] = (bf16_rn(expf(tr.w)) << 16) | bf16_rn(expf(tr.z));
            }
            // rows 24..31 -> SMEM (each element written by exactly one thread)
            #pragma unroll
            for (int r = REG_ROWS; r < 32; ++r) {
                float4 tr = *(const float4*)(trow + (size_t)r * T);
                unsigned lo = (bf16_rn(expf(tr.y)) << 16) | bf16_rn(expf(tr.x));
                unsigned hi = (bf16_rn(expf(tr.w)) << 16) | bf16_rn(expf(tr.z));
                *(uint2*)(EsmH + (size_t)(is * 8 + (r - REG_ROWS)) * T + jg4) =
                    make_uint2(lo, hi);
            }
        }
        BAR_LSE();   // EsmH visible to nobody else, but keep ordering tidy

        const float*          Prow = Psm + i0;
        const unsigned short* erow = EsmH + (size_t)(is * 8) * T + jg4;
        float*                accw = accp + is * T + jg4;
        float m_P = m0;

        for (int t = 1; t < L; ++t) {
            float emit = 0.f;
            if (tid < T) emit = gl[(size_t)t * T + tid];   // prefetch

            float a0 = 0.f, a1 = 0.f, a2 = 0.f, a3 = 0.f;
            #define FMA2(U0, U1, PP)                                           \
                a0 = fmaf(PP, __uint_as_float((U0) << 16), a0);                \
                a1 = fmaf(PP, __uint_as_float((U0) & 0xffff0000u), a1);        \
                a2 = fmaf(PP, __uint_as_float((U1) << 16), a2);                \
                a3 = fmaf(PP, __uint_as_float((U1) & 0xffff0000u), a3);
            #pragma unroll
            for (int r = 0; r < REG_ROWS; r += 4) {
                float4 p4 = *(const float4*)(Prow + r);
                FMA2(eR[2*(r+0)+0], eR[2*(r+0)+1], p4.x)
                FMA2(eR[2*(r+1)+0], eR[2*(r+1)+1], p4.y)
                FMA2(eR[2*(r+2)+0], eR[2*(r+2)+1], p4.z)
                FMA2(eR[2*(r+3)+0], eR[2*(r+3)+1], p4.w)
            }
            #pragma unroll
            for (int r = 0; r < 8; r += 4) {
                float4 p4 = *(const float4*)(Prow + REG_ROWS + r);
                uint2 e0 = *(const uint2*)(erow + (size_t)(r + 0) * T);
                uint2 e1 = *(const uint2*)(erow + (size_t)(r + 1) * T);
                uint2 e2 = *(const uint2*)(erow + (size_t)(r + 2) * T);
                uint2 e3 = *(const uint2*)(erow + (size_t)(r + 3) * T);
                FMA2(e0.x, e0.y, p4.x)
                FMA2(e1.x, e1.y, p4.y)
                FMA2(e2.x, e2.y, p4.z)
                FMA2(e3.x, e3.y, p4.w)
            }
            #undef FMA2
            *(float4*)accw = make_float4(a0, a1, a2, a3);
            BAR_LSE();

            if (tid < T) {
                float asum = 0.f;
                #pragma unroll
                for (int s2 = 0; s2 < 8; ++s2) asum += accp[s2 * T + tid];
                const float* rr = redf + (((t - 1) & 1) << 3);   // stale max
                float mnext = rr[0];
                #pragma unroll
                for (int w = 1; w < 8; ++w) mnext = fmaxf(mnext, rr[w]);
                float dsn = m_P + logf(asum) + emit;
                dsbuf[tid] = dsn;
                float wmax = dsn;
                #pragma unroll
                for (int o = 16; o; o >>= 1) wmax = fmaxf(wmax, __shfl_xor_sync(0xffffffffu, wmax, o));
                if (lane == 0) redf[((t & 1) << 3) + wid] = wmax;
                Psm[tid] = exp2f((dsn - mnext) * L2E);
                m_P = mnext;
            }
            BAR_LSE();
        }
    } else {
        // ---------------- Viterbi group (4 warps, certified pruning) ----------------
        const int vtid  = tid - 512;
        const int vwid  = vtid >> 5;
        const int vlane = vtid & 31;
        const int j0  = 2 * vtid;
        const int i0c = 2 * vtid;

        for (int t = 1; t < L; ++t) {
            float2 em  = *(const float2*)(gl + (size_t)t * T + j0);
            float2 v2  = *(const float2*)(vssm + i0c);
            float2 rn2 = *(const float2*)(rmin + i0c);
            float2 rx2 = *(const float2*)(rmax + i0c);

            float sthr = fmaxf(v2.x + rn2.x, v2.y + rn2.y);
            #pragma unroll
            for (int o = 16; o; o >>= 1) sthr = fmaxf(sthr, __shfl_xor_sync(0xffffffffu, sthr, o));
            if (vlane == 0) vred[vwid] = sthr;
            BAR_VIT();
            float thresh = fmaxf(fmaxf(vred[0], vred[1]), fmaxf(vred[2], vred[3]));

            int q0 = (v2.x + rx2.x >= thresh) ? 1 : 0;
            int q1 = (v2.y + rx2.y >= thresh) ? 1 : 0;
            int cnt = q0 + q1;
            int incl = cnt;
            #pragma unroll
            for (int o = 1; o < 32; o <<= 1) {
                int n = __shfl_up_sync(0xffffffffu, incl, o);
                if (vlane >= o) incl += n;
            }
            int excl = incl - cnt;
            if (vlane == 31) wcnt[vwid] = incl;
            BAR_VIT();
            int base = 0;
            #pragma unroll
            for (int w = 0; w < 4; ++w) base += (w < vwid) ? wcnt[w] : 0;
            int nc = wcnt[0] + wcnt[1] + wcnt[2] + wcnt[3];
            int pos = base + excl;
            if (q0) { cidx[pos] = i0c;     cval[pos] = v2.x; pos++; }
            if (q1) { cidx[pos] = i0c + 1; cval[pos] = v2.y; }
            BAR_VIT();

            float b1 = NEG_INF, b2 = NEG_INF;
            int x1 = 0, x2 = 0;
            int c = 0;
            for (; c + 4 <= nc; c += 4) {
                int   ia = cidx[c], ibx = cidx[c+1], ic = cidx[c+2], id = cidx[c+3];
                float va = cval[c], vb = cval[c+1], vc = cval[c+2], vd = cval[c+3];
                float2 ta = *(const float2*)(trans + (size_t)ia  * T + j0);
                float2 tb = *(const float2*)(trans + (size_t)ibx * T + j0);
                float2 tc = *(const float2*)(trans + (size_t)ic  * T + j0);
                float2 td = *(const float2*)(trans + (size_t)id  * T + j0);
                float c1, c2;
                c1 = va + ta.x; if (c1 > b1) { b1 = c1; x1 = ia; }
                c2 = va + ta.y; if (c2 > b2) { b2 = c2; x2 = ia; }
                c1 = vb + tb.x; if (c1 > b1) { b1 = c1; x1 = ibx; }
                c2 = vb + tb.y; if (c2 > b2) { b2 = c2; x2 = ibx; }
                c1 = vc + tc.x; if (c1 > b1) { b1 = c1; x1 = ic; }
                c2 = vc + tc.y; if (c2 > b2) { b2 = c2; x2 = ic; }
                c1 = vd + td.x; if (c1 > b1) { b1 = c1; x1 = id; }
                c2 = vd + td.y; if (c2 > b2) { b2 = c2; x2 = id; }
            }
            for (; c < nc; ++c) {
                int   ia = cidx[c];
                float va = cval[c];
                float2 ta = *(const float2*)(trans + (size_t)ia * T + j0);
                float c1 = va + ta.x; if (c1 > b1) { b1 = c1; x1 = ia; }
                float c2 = va + ta.y; if (c2 > b2) { b2 = c2; x2 = ia; }
            }

            *(float2*)(vssm + j0) = make_float2(b1 + em.x, b2 + em.y);
            *(unsigned short*)(g_hist + ((size_t)t * B + b) * T + j0) =
                (unsigned short)((unsigned)x1 | ((unsigned)x2 << 8));
            BAR_VIT();
        }
    }
    __syncthreads();   // join groups

    // ================= epilogue (full block) =================
    // denominator: logsumexp(ds + end)
    {
        float xd = NEG_INF;
        if (tid < T) xd = dsbuf[tid] + end_t[tid];
        float v = xd;
        #pragma unroll
        for (int o = 16; o; o >>= 1) v = fmaxf(v, __shfl_xor_sync(0xffffffffu, v, o));
        if (lane == 0) redf[wid] = v;
        __syncthreads();
        float m2 = redf[0];
        #pragma unroll
        for (int w = 1; w < THREADS / 32; ++w) m2 = fmaxf(m2, redf[w]);
        float cs = (tid < T) ? exp2f((xd - m2) * L2E) : 0.f;
        #pragma unroll
        for (int o = 16; o; o >>= 1) cs += __shfl_xor_sync(0xffffffffu, cs, o);
        __syncthreads();
        if (lane == 0) redf[wid] = cs;
        __syncthreads();
        if (tid == 0) {
            float ssum = 0.f;
            #pragma unroll
            for (int w = 0; w < THREADS / 32; ++w) ssum += redf[w];
            g_den[b] = m2 + logf(ssum);
        }
    }
    // viterbi last tag: argmax(vs + end), lowest index on ties
    {
        float xv = NEG_INF;
        int idx = 0x7fffffff;
        if (tid < T) { xv = vssm[tid] + end_t[tid]; idx = tid; }
        #pragma unroll
        for (int o = 16; o; o >>= 1) {
            float ov = __shfl_xor_sync(0xffffffffu, xv, o);
            int   oi = __shfl_xor_sync(0xffffffffu, idx, o);
            if (ov > xv || (ov == xv && oi < idx)) { xv = ov; idx = oi; }
        }
        __syncthreads();
        if (lane == 0) { redf[wid] = xv; redi[wid] = idx; }
        __syncthreads();
        if (tid == 0) {
            float bv = redf[0]; int bi = redi[0];
            #pragma unroll
            for (int w = 1; w < THREADS / 32; ++w) {
                float ov = redf[w]; int oi = redi[w];
                if (ov > bv || (ov == bv && oi < bi)) { bv = ov; bi = oi; }
            }
            vibc[0] = bi;
        }
        __syncthreads();
    }
    const int last = vibc[0];

    // backtrack: stage this batch's history into SMEM (reuses loop region)
    unsigned char* hsm = (unsigned char*)(sm);   // L*T <= 131072
    for (int f = tid; f < L * (T / 16); f += THREADS) {
        int row = f >> 4;
        int off = f & 15;
        ((uint4*)hsm)[f] = ((const uint4*)(g_hist + ((size_t)row * B + b) * T))[off];
    }
    __syncthreads();

    float* outp = out + (size_t)b * S;
    for (int s = L + tid; s < S; s += THREADS) outp[s] = 0.0f;  // masked -> 0
    if (tid == 0) {
        int tag = last;
        outp[L - 1] = (float)tag;
        for (int t = L - 2; t >= 0; --t) {
            tag = hsm[(t + 1) * T + tag];
            outp[t] = (float)tag;
        }
    }
}

// ---------------- numerator ----------------
__global__ void __launch_bounds__(256)
crf_num(const float* __restrict__ logits, const int* __restrict__ mask,
        const int* __restrict__ labels, const float* __restrict__ start_t,
        const float* __restrict__ end_t, const float* __restrict__ trans) {
    __shared__ float redf[8];
    __shared__ int   redi[8];
    const int b = blockIdx.x;
    const int tid = threadIdx.x;
    const int* lab = labels + (size_t)b * S;
    const float* gl = logits + (size_t)b * S * T;
    const int* mrow = mask + (size_t)b * S;

    float part = 0.f;
    int cnt = 0;
    for (int s = tid; s < S; s += 256) cnt += (mrow[s] != 0);
    for (int s = 1 + tid; s < S; s += 256) {
        if (mrow[s]) {
            int ls = lab[s];
            int lp = lab[s - 1];
            part += trans[lp * T + ls] + gl[(size_t)s * T + ls];
        }
    }
    #pragma unroll
    for (int o = 16; o; o >>= 1) {
        part += __shfl_xor_sync(0xffffffffu, part, o);
        cnt  += __shfl_xor_sync(0xffffffffu, cnt, o);
    }
    if ((tid & 31) == 0) { redf[tid >> 5] = part; redi[tid >> 5] = cnt; }
    __syncthreads();
    if (tid == 0) {
        float s = 0.f; int L = 0;
        #pragma unroll
        for (int w = 0; w < 8; ++w) { s += redf[w]; L += redi[w]; }
        int l0 = lab[0];
        int ll = lab[L - 1];
        g_num[b] = s + start_t[l0] + gl[l0] + end_t[ll];
    }
}

// ---------------- loss ----------------
__global__ void __launch_bounds__(128)
crf_loss(float* __restrict__ out) {
    __shared__ float redf[4];
    const int tid = threadIdx.x;
    float d = g_num[tid] - g_den[tid];
    #pragma unroll
    for (int o = 16; o; o >>= 1) d += __shfl_xor_sync(0xffffffffu, d, o);
    if ((tid & 31) == 0) redf[tid >> 5] = d;
    __syncthreads();
    if (tid == 0) {
        float s = redf[0] + redf[1] + redf[2] + redf[3];
        out[(size_t)B * S] = -(s / (float)B);
    }
}

// ---------------- launch ----------------
extern "C" void kernel_launch(void* const* d_in, const int* in_sizes, int n_in,
                              void* d_out, int out_size) {
    const float* logits = (const float*)d_in[0];
    const int*   mask   = (const int*)d_in[1];
    const int*   labels = (const int*)d_in[2];
    const float* start  = (const float*)d_in[3];
    const float* endt   = (const float*)d_in[4];
    const float* trans  = (const float*)d_in[5];
    float*       out    = (float*)d_out;

    cudaFuncSetAttribute(crf_main, cudaFuncAttributeMaxDynamicSharedMemorySize, SMEM_BYTES);

    crf_main<<<B, THREADS, SMEM_BYTES>>>(logits, mask, start, endt, trans, out);
    crf_num<<<B, 256>>>(logits, mask, labels, start, endt, trans);
    crf_loss<<<1, 128>>>(out);
}